// round 4
// baseline (speedup 1.0000x reference)
#include <cuda_runtime.h>
#include <cuda_bf16.h>
#include <cstdint>

#define DEVI static __device__ __forceinline__

static constexpr int MT = 64 * 197;   // 12608 rows
static constexpr int DD = 768;
static constexpr int HH = 3072;
static constexpr float FBIG = 3.0e38f;

// Scratch (allocation-free rule: __device__ globals)
__device__ uint8_t g_xq[MT * DD];                 // u8 activation codes q
__device__ int8_t  g_w1q[HH * DD];                // s8 weight codes
__device__ int8_t  g_w2q[DD * HH];
__device__ float   g_mid[(size_t)MT * HH];        // gelu output fp32
__device__ uint8_t g_gq[(size_t)MT * HH];         // u8 codes of g
__device__ int     g_cs1[HH];                     // colsum of w1 codes
__device__ int     g_cs2[DD];                     // colsum of w2 codes
__device__ float   g_stats[6];                    // xmin,xmax,w1max,w2max,gmin,gmax

DEVI void atomicMinF(float* a, float v) {
    int* ai = (int*)a;
    int old = *ai;
    while (__int_as_float(old) > v) {
        int as = old;
        old = atomicCAS(ai, as, __float_as_int(v));
        if (old == as) break;
    }
}
DEVI void atomicMaxF(float* a, float v) {
    int* ai = (int*)a;
    int old = *ai;
    while (__int_as_float(old) < v) {
        int as = old;
        old = atomicCAS(ai, as, __float_as_int(v));
        if (old == as) break;
    }
}

__global__ void k_init() {
    g_stats[0] = FBIG;  g_stats[1] = -FBIG;
    g_stats[2] = 0.f;   g_stats[3] = 0.f;
    g_stats[4] = FBIG;  g_stats[5] = -FBIG;
}

__global__ void k_minmax(const float* __restrict__ x, int n4, int idx) {
    float lo = FBIG, hi = -FBIG;
    int st = gridDim.x * blockDim.x;
    for (int i = blockIdx.x * blockDim.x + threadIdx.x; i < n4; i += st) {
        float4 v = ((const float4*)x)[i];
        lo = fminf(lo, fminf(fminf(v.x, v.y), fminf(v.z, v.w)));
        hi = fmaxf(hi, fmaxf(fmaxf(v.x, v.y), fmaxf(v.z, v.w)));
    }
    for (int o = 16; o; o >>= 1) {
        lo = fminf(lo, __shfl_xor_sync(0xffffffffu, lo, o));
        hi = fmaxf(hi, __shfl_xor_sync(0xffffffffu, hi, o));
    }
    __shared__ float slo[8], shi[8];
    int w = threadIdx.x >> 5;
    if ((threadIdx.x & 31) == 0) { slo[w] = lo; shi[w] = hi; }
    __syncthreads();
    if (threadIdx.x == 0) {
        for (int i = 1; i < 8; i++) { lo = fminf(lo, slo[i]); hi = fmaxf(hi, shi[i]); }
        atomicMinF(&g_stats[idx], lo);
        atomicMaxF(&g_stats[idx + 1], hi);
    }
}

__global__ void k_absmax(const float* __restrict__ w, int n4, int idx) {
    float hi = 0.f;
    int st = gridDim.x * blockDim.x;
    for (int i = blockIdx.x * blockDim.x + threadIdx.x; i < n4; i += st) {
        float4 v = ((const float4*)w)[i];
        hi = fmaxf(hi, fmaxf(fmaxf(fabsf(v.x), fabsf(v.y)), fmaxf(fabsf(v.z), fabsf(v.w))));
    }
    for (int o = 16; o; o >>= 1) hi = fmaxf(hi, __shfl_xor_sync(0xffffffffu, hi, o));
    __shared__ float shi[8];
    int w8 = threadIdx.x >> 5;
    if ((threadIdx.x & 31) == 0) shi[w8] = hi;
    __syncthreads();
    if (threadIdx.x == 0) {
        for (int i = 1; i < 8; i++) hi = fmaxf(hi, shi[i]);
        atomicMaxF(&g_stats[idx], hi);
    }
}

// activation quant: q = clip(rint(v/s)+zp, 0, 255), store q as u8 (exact)
DEVI uint8_t qa(float v, float s, float zp) {
    float q = fminf(fmaxf(rintf(v / s) + zp, 0.f), 255.f);
    return (uint8_t)(int)q;
}

__global__ void k_quant_x(const float* __restrict__ x, int n4) {
    float lo = g_stats[0], hi = g_stats[1];
    float s = fmaxf(hi - lo, 1e-8f) / 255.0f;
    float zp = rintf(-lo / s);
    uchar4* qp = (uchar4*)g_xq;
    int st = gridDim.x * blockDim.x;
    for (int i = blockIdx.x * blockDim.x + threadIdx.x; i < n4; i += st) {
        float4 v = ((const float4*)x)[i];
        qp[i] = make_uchar4(qa(v.x, s, zp), qa(v.y, s, zp), qa(v.z, s, zp), qa(v.w, s, zp));
    }
}

__global__ void k_quant_g(int n4) {
    float lo = g_stats[4], hi = g_stats[5];
    float s = fmaxf(hi - lo, 1e-8f) / 255.0f;
    float zp = rintf(-lo / s);
    uchar4* qp = (uchar4*)g_gq;
    const float* x = g_mid;
    int st = gridDim.x * blockDim.x;
    for (int i = blockIdx.x * blockDim.x + threadIdx.x; i < n4; i += st) {
        float4 v = ((const float4*)x)[i];
        qp[i] = make_uchar4(qa(v.x, s, zp), qa(v.y, s, zp), qa(v.z, s, zp), qa(v.w, s, zp));
    }
}

DEVI int8_t qw(float v, float s) {
    float q = fminf(fmaxf(rintf(v / s), -128.f), 127.f);
    return (int8_t)(int)q;
}

__global__ void k_quant_w(const float* __restrict__ w, int n4, int idx, int which) {
    float s = fmaxf(g_stats[idx], 1e-8f) / 127.0f;
    char4* qp = (char4*)(which ? g_w2q : g_w1q);
    int st = gridDim.x * blockDim.x;
    for (int i = blockIdx.x * blockDim.x + threadIdx.x; i < n4; i += st) {
        float4 v = ((const float4*)w)[i];
        qp[i] = make_char4(qw(v.x, s), qw(v.y, s), qw(v.z, s), qw(v.w, s));
    }
}

// column sums of s8 weight codes: cs[n] = sum_k w[n,k]
// NOTE: selects __device__ globals inside device code (host cannot pass
// __device__ symbol addresses as kernel args — that was the R3 bug).
__global__ void k_colsum(int which) {
    const int8_t* w = which ? g_w2q : g_w1q;
    int* out = which ? g_cs2 : g_cs1;
    const int K4 = which ? (HH / 4) : (DD / 4);
    const int N  = which ? DD : HH;
    int gw = blockIdx.x * (blockDim.x >> 5) + (threadIdx.x >> 5);
    int lane = threadIdx.x & 31;
    if (gw >= N) return;
    const int* wr = (const int*)w + (size_t)gw * K4;
    int s = 0;
    for (int i = lane; i < K4; i += 32) s = __dp4a(wr[i], 0x01010101, s);
    for (int o = 16; o; o >>= 1) s += __shfl_xor_sync(0xffffffffu, s, o);
    if (lane == 0) out[gw] = s;
}

DEVI float igelu(float x) {
    float tt = x * 0.70710678118654752440f;
    float at = fminf(fabsf(tt), 1.769f);
    float dd = at - 1.769f;
    float L = fmaf(-0.2888f, dd * dd, 1.0f);
    L = copysignf(L, tt);
    return x * 0.5f * (1.0f + L);
}

// ---------------------------------------------------------------------------
// int8 GEMM: out[m,n] = sAW * (sum_k qa[m,k]*qw[n,k] - zp*colsum[n]) + bias[n]
// BM=128, BN=256, BK=64 codes, 512 threads, 3-stage cp.async ring.
// Warp grid 2x8, warp tile 64x32, mma.m16n8k32.u8.s8.s32.
// ---------------------------------------------------------------------------
template <int EPI>
__global__ void __launch_bounds__(512, 1) k_gemm_i8(const float* __restrict__ bias,
                                                    float* __restrict__ Cout) {
    constexpr int Mn = MT;
    constexpr int Nn = (EPI == 1) ? HH : DD;
    constexpr int Kn = (EPI == 1) ? DD : HH;
    constexpr int BM = 128, BN = 256, BK = 64;
    constexpr int KT = Kn / BK;
    constexpr int ROWB = 80;                      // padded row stride (bytes)
    constexpr int STAGE = (BM + BN) * ROWB;       // 30720 B

    const uint8_t* __restrict__ A = (EPI == 1) ? g_xq : g_gq;
    const int8_t*  __restrict__ B = (EPI == 1) ? g_w1q : g_w2q;
    const int*     __restrict__ CS = (EPI == 1) ? g_cs1 : g_cs2;
    float* __restrict__ C = (EPI == 1) ? g_mid : Cout;

    extern __shared__ char smem[];

    const int tid = threadIdx.x;
    const int warp = tid >> 5, lane = tid & 31;
    const int wm = warp & 1, wn = warp >> 1;      // 2 x 8 warps; tile 64x32
    const int g = lane >> 2, t = lane & 3;
    const int mBase = blockIdx.x * BM, nBase = blockIdx.y * BN;

    int acc[4][4][4];
#pragma unroll
    for (int i = 0; i < 4; i++)
#pragma unroll
        for (int j = 0; j < 4; j++)
#pragma unroll
            for (int k = 0; k < 4; k++) acc[i][j][k] = 0;

    // ---- stage loader: 1536 chunks of 16B ----
    auto issue = [&](int s) {
        char* sb = smem + (s % 3) * STAGE;
        const int kOff = s * BK;
#pragma unroll
        for (int ci = tid; ci < 1536; ci += 512) {
            int row = ci >> 2, cc = ci & 3;
            uint32_t dst = (uint32_t)__cvta_generic_to_shared(sb + row * ROWB + cc * 16);
            if (row < BM) {
                int grow = mBase + row;
                bool ok = grow < Mn;
                int safe = ok ? grow : (Mn - 1);
                const uint8_t* gp = A + (size_t)safe * Kn + kOff + cc * 16;
                int sz = ok ? 16 : 0;
                asm volatile("cp.async.cg.shared.global [%0], [%1], 16, %2;\n"
                             :: "r"(dst), "l"(gp), "r"(sz));
            } else {
                const int8_t* gp = B + (size_t)(nBase + row - BM) * Kn + kOff + cc * 16;
                asm volatile("cp.async.cg.shared.global [%0], [%1], 16, %2;\n"
                             :: "r"(dst), "l"(gp), "r"(16));
            }
        }
        asm volatile("cp.async.commit_group;\n");
    };

    auto compute = [&](int s) {
        const uint32_t* S32 = (const uint32_t*)(smem + (s % 3) * STAGE);
        const uint32_t* A32 = S32;
        const uint32_t* B32 = S32 + BM * (ROWB / 4);
#pragma unroll
        for (int ks = 0; ks < 2; ks++) {
            uint32_t af[4][4], bf[4][2];
#pragma unroll
            for (int i = 0; i < 4; i++) {
                int r0 = (wm * 64 + i * 16 + g) * (ROWB / 4);
                af[i][0] = A32[r0 + ks * 8 + t];
                af[i][1] = A32[r0 + 8 * (ROWB / 4) + ks * 8 + t];
                af[i][2] = A32[r0 + ks * 8 + 4 + t];
                af[i][3] = A32[r0 + 8 * (ROWB / 4) + ks * 8 + 4 + t];
            }
#pragma unroll
            for (int j = 0; j < 4; j++) {
                int n0 = (wn * 32 + j * 8 + g) * (ROWB / 4);
                bf[j][0] = B32[n0 + ks * 8 + t];
                bf[j][1] = B32[n0 + ks * 8 + 4 + t];
            }
#pragma unroll
            for (int i = 0; i < 4; i++)
#pragma unroll
                for (int j = 0; j < 4; j++) {
                    asm volatile(
                        "mma.sync.aligned.m16n8k32.row.col.s32.u8.s8.s32 "
                        "{%0,%1,%2,%3}, {%4,%5,%6,%7}, {%8,%9}, {%0,%1,%2,%3};\n"
                        : "+r"(acc[i][j][0]), "+r"(acc[i][j][1]),
                          "+r"(acc[i][j][2]), "+r"(acc[i][j][3])
                        : "r"(af[i][0]), "r"(af[i][1]), "r"(af[i][2]), "r"(af[i][3]),
                          "r"(bf[j][0]), "r"(bf[j][1]));
                }
        }
    };

    issue(0);
    issue(1);
    for (int kt = 0; kt < KT; kt++) {
        if (kt + 2 < KT) {
            issue(kt + 2);
            asm volatile("cp.async.wait_group 2;\n" ::: "memory");
        } else if (kt + 1 < KT) {
            asm volatile("cp.async.wait_group 1;\n" ::: "memory");
        } else {
            asm volatile("cp.async.wait_group 0;\n" ::: "memory");
        }
        __syncthreads();
        compute(kt);
        __syncthreads();
    }

    // ---- epilogue ----
    float sAW;
    int zpi;
    if (EPI == 1) {
        float sx = fmaxf(g_stats[1] - g_stats[0], 1e-8f) / 255.0f;
        zpi = (int)rintf(-g_stats[0] / sx);
        float sw = fmaxf(g_stats[2], 1e-8f) / 127.0f;
        sAW = sx * sw;
    } else {
        float sx = fmaxf(g_stats[5] - g_stats[4], 1e-8f) / 255.0f;
        zpi = (int)rintf(-g_stats[4] / sx);
        float sw = fmaxf(g_stats[3], 1e-8f) / 127.0f;
        sAW = sx * sw;
    }

    float lo = FBIG, hi = -FBIG;
#pragma unroll
    for (int j = 0; j < 4; j++) {
        int c = nBase + wn * 32 + j * 8 + 2 * t;
        float b0 = __ldg(bias + c), b1 = __ldg(bias + c + 1);
        int corr0 = zpi * __ldg(CS + c), corr1 = zpi * __ldg(CS + c + 1);
#pragma unroll
        for (int i = 0; i < 4; i++) {
            int row0 = mBase + wm * 64 + i * 16 + g;
            float v0 = (float)(acc[i][j][0] - corr0) * sAW + b0;
            float v1 = (float)(acc[i][j][1] - corr1) * sAW + b1;
            float v2 = (float)(acc[i][j][2] - corr0) * sAW + b0;
            float v3 = (float)(acc[i][j][3] - corr1) * sAW + b1;
            if (EPI == 1) {
                v0 = igelu(v0); v1 = igelu(v1); v2 = igelu(v2); v3 = igelu(v3);
            }
            if (row0 < Mn) {
                if (EPI == 1) {
                    lo = fminf(lo, fminf(v0, v1));
                    hi = fmaxf(hi, fmaxf(v0, v1));
                }
                *(float2*)(C + (size_t)row0 * Nn + c) = make_float2(v0, v1);
            }
            if (row0 + 8 < Mn) {
                if (EPI == 1) {
                    lo = fminf(lo, fminf(v2, v3));
                    hi = fmaxf(hi, fmaxf(v2, v3));
                }
                *(float2*)(C + (size_t)(row0 + 8) * Nn + c) = make_float2(v2, v3);
            }
        }
    }

    if (EPI == 1) {
        for (int o = 16; o; o >>= 1) {
            lo = fminf(lo, __shfl_xor_sync(0xffffffffu, lo, o));
            hi = fmaxf(hi, __shfl_xor_sync(0xffffffffu, hi, o));
        }
        __shared__ float rlo[16], rhi[16];
        if (lane == 0) { rlo[warp] = lo; rhi[warp] = hi; }
        __syncthreads();
        if (tid == 0) {
            for (int i = 1; i < 16; i++) { lo = fminf(lo, rlo[i]); hi = fmaxf(hi, rhi[i]); }
            atomicMinF(&g_stats[4], lo);
            atomicMaxF(&g_stats[5], hi);
        }
    }
}

extern "C" void kernel_launch(void* const* d_in, const int* in_sizes, int n_in,
                              void* d_out, int out_size) {
    const float* x  = (const float*)d_in[0];
    const float* w1 = (const float*)d_in[1];
    const float* b1 = (const float*)d_in[2];
    const float* w2 = (const float*)d_in[3];
    const float* b2 = (const float*)d_in[4];
    float* out = (float*)d_out;

    constexpr int SMEM_BYTES = 3 * (128 + 256) * 80;   // 92160
    cudaFuncSetAttribute(k_gemm_i8<1>, cudaFuncAttributeMaxDynamicSharedMemorySize, SMEM_BYTES);
    cudaFuncSetAttribute(k_gemm_i8<2>, cudaFuncAttributeMaxDynamicSharedMemorySize, SMEM_BYTES);

    k_init<<<1, 1>>>();
    k_minmax<<<1024, 256>>>(x, MT * DD / 4, 0);
    k_absmax<<<512, 256>>>(w1, HH * DD / 4, 2);
    k_absmax<<<512, 256>>>(w2, DD * HH / 4, 3);
    k_quant_x<<<2048, 256>>>(x, MT * DD / 4);
    k_quant_w<<<512, 256>>>(w1, HH * DD / 4, 2, 0);
    k_quant_w<<<512, 256>>>(w2, DD * HH / 4, 3, 1);
    k_colsum<<<(HH + 7) / 8, 256>>>(0);
    k_colsum<<<(DD + 7) / 8, 256>>>(1);

    dim3 grid1((MT + 127) / 128, HH / 256);
    k_gemm_i8<1><<<grid1, 512, SMEM_BYTES>>>(b1, nullptr);

    k_quant_g<<<4096, 256>>>((int)((size_t)MT * HH / 4));

    dim3 grid2((MT + 127) / 128, DD / 256);
    k_gemm_i8<2><<<grid2, 512, SMEM_BYTES>>>(b2, out);
}

// round 5
// speedup vs baseline: 2.4988x; 2.4988x over previous
#include <cuda_runtime.h>
#include <cuda_bf16.h>
#include <cstdint>

#define DEVI static __device__ __forceinline__

static constexpr int MT = 64 * 197;   // 12608 rows
static constexpr int DD = 768;
static constexpr int HH = 3072;
static constexpr float FBIG = 3.0e38f;

// Scratch (allocation-free rule: __device__ globals)
__device__ __nv_bfloat16 g_xq[MT * DD];          // (q - zp) codes of x, exact ints in bf16
__device__ __nv_bfloat16 g_w1q[HH * DD];         // w1 codes
__device__ __nv_bfloat16 g_w2q[DD * HH];         // w2 codes
__device__ float         g_mid[(size_t)MT * HH]; // gelu output fp32
__device__ __nv_bfloat16 g_gq[(size_t)MT * HH];  // (q - zp) codes of g
__device__ float         g_stats[6];             // xmin,xmax,w1max,w2max,gmin,gmax

DEVI void atomicMinF(float* a, float v) {
    int* ai = (int*)a;
    int old = *ai;
    while (__int_as_float(old) > v) {
        int as = old;
        old = atomicCAS(ai, as, __float_as_int(v));
        if (old == as) break;
    }
}
DEVI void atomicMaxF(float* a, float v) {
    int* ai = (int*)a;
    int old = *ai;
    while (__int_as_float(old) < v) {
        int as = old;
        old = atomicCAS(ai, as, __float_as_int(v));
        if (old == as) break;
    }
}

__global__ void k_init() {
    g_stats[0] = FBIG;  g_stats[1] = -FBIG;
    g_stats[2] = 0.f;   g_stats[3] = 0.f;
    g_stats[4] = FBIG;  g_stats[5] = -FBIG;
}

__global__ void k_minmax(const float* __restrict__ x, int n4, int idx) {
    float lo = FBIG, hi = -FBIG;
    int st = gridDim.x * blockDim.x;
    for (int i = blockIdx.x * blockDim.x + threadIdx.x; i < n4; i += st) {
        float4 v = ((const float4*)x)[i];
        lo = fminf(lo, fminf(fminf(v.x, v.y), fminf(v.z, v.w)));
        hi = fmaxf(hi, fmaxf(fmaxf(v.x, v.y), fmaxf(v.z, v.w)));
    }
    for (int o = 16; o; o >>= 1) {
        lo = fminf(lo, __shfl_xor_sync(0xffffffffu, lo, o));
        hi = fmaxf(hi, __shfl_xor_sync(0xffffffffu, hi, o));
    }
    __shared__ float slo[8], shi[8];
    int w = threadIdx.x >> 5;
    if ((threadIdx.x & 31) == 0) { slo[w] = lo; shi[w] = hi; }
    __syncthreads();
    if (threadIdx.x == 0) {
        for (int i = 1; i < 8; i++) { lo = fminf(lo, slo[i]); hi = fmaxf(hi, shi[i]); }
        atomicMinF(&g_stats[idx], lo);
        atomicMaxF(&g_stats[idx + 1], hi);
    }
}

__global__ void k_absmax(const float* __restrict__ w, int n4, int idx) {
    float hi = 0.f;
    int st = gridDim.x * blockDim.x;
    for (int i = blockIdx.x * blockDim.x + threadIdx.x; i < n4; i += st) {
        float4 v = ((const float4*)w)[i];
        hi = fmaxf(hi, fmaxf(fmaxf(fabsf(v.x), fabsf(v.y)), fmaxf(fabsf(v.z), fabsf(v.w))));
    }
    for (int o = 16; o; o >>= 1) hi = fmaxf(hi, __shfl_xor_sync(0xffffffffu, hi, o));
    __shared__ float shi[8];
    int w8 = threadIdx.x >> 5;
    if ((threadIdx.x & 31) == 0) shi[w8] = hi;
    __syncthreads();
    if (threadIdx.x == 0) {
        for (int i = 1; i < 8; i++) hi = fmaxf(hi, shi[i]);
        atomicMaxF(&g_stats[idx], hi);
    }
}

DEVI float quant_act_one(float v, float s, float zp) {
    return fminf(fmaxf(rintf(v / s) + zp, 0.f), 255.f) - zp;
}

__global__ void k_quant_x(const float* __restrict__ x, int n4) {
    float lo = g_stats[0], hi = g_stats[1];
    float s = fmaxf(hi - lo, 1e-8f) / 255.0f;
    float zp = rintf(-lo / s);
    __nv_bfloat162* qp = (__nv_bfloat162*)g_xq;
    int st = gridDim.x * blockDim.x;
    for (int i = blockIdx.x * blockDim.x + threadIdx.x; i < n4; i += st) {
        float4 v = ((const float4*)x)[i];
        qp[2 * i]     = __floats2bfloat162_rn(quant_act_one(v.x, s, zp), quant_act_one(v.y, s, zp));
        qp[2 * i + 1] = __floats2bfloat162_rn(quant_act_one(v.z, s, zp), quant_act_one(v.w, s, zp));
    }
}

__global__ void k_quant_g(int n4) {
    float lo = g_stats[4], hi = g_stats[5];
    float s = fmaxf(hi - lo, 1e-8f) / 255.0f;
    float zp = rintf(-lo / s);
    __nv_bfloat162* qp = (__nv_bfloat162*)g_gq;
    const float* x = g_mid;
    int st = gridDim.x * blockDim.x;
    for (int i = blockIdx.x * blockDim.x + threadIdx.x; i < n4; i += st) {
        float4 v = ((const float4*)x)[i];
        qp[2 * i]     = __floats2bfloat162_rn(quant_act_one(v.x, s, zp), quant_act_one(v.y, s, zp));
        qp[2 * i + 1] = __floats2bfloat162_rn(quant_act_one(v.z, s, zp), quant_act_one(v.w, s, zp));
    }
}

__global__ void k_quant_w(const float* __restrict__ w, int n4, int idx, int which) {
    float s = fmaxf(g_stats[idx], 1e-8f) / 127.0f;
    __nv_bfloat162* qp = (__nv_bfloat162*)(which ? g_w2q : g_w1q);
    int st = gridDim.x * blockDim.x;
    for (int i = blockIdx.x * blockDim.x + threadIdx.x; i < n4; i += st) {
        float4 v = ((const float4*)w)[i];
        float q0 = fminf(fmaxf(rintf(v.x / s), -128.f), 127.f);
        float q1 = fminf(fmaxf(rintf(v.y / s), -128.f), 127.f);
        float q2 = fminf(fmaxf(rintf(v.z / s), -128.f), 127.f);
        float q3 = fminf(fmaxf(rintf(v.w / s), -128.f), 127.f);
        qp[2 * i]     = __floats2bfloat162_rn(q0, q1);
        qp[2 * i + 1] = __floats2bfloat162_rn(q2, q3);
    }
}

DEVI float igelu(float x) {
    float tt = x * 0.70710678118654752440f;
    float at = fminf(fabsf(tt), 1.769f);
    float dd = at - 1.769f;
    float L = fmaf(-0.2888f, dd * dd, 1.0f);
    L = copysignf(L, tt);
    return x * 0.5f * (1.0f + L);
}

DEVI void ldsm_x4(uint32_t& r0, uint32_t& r1, uint32_t& r2, uint32_t& r3, uint32_t addr) {
    asm volatile("ldmatrix.sync.aligned.m8n8.x4.shared.b16 {%0,%1,%2,%3}, [%4];"
                 : "=r"(r0), "=r"(r1), "=r"(r2), "=r"(r3) : "r"(addr));
}
DEVI void hmma(float* c, const uint32_t* a, const uint32_t* b) {
    asm volatile(
        "mma.sync.aligned.m16n8k16.row.col.f32.bf16.bf16.f32 "
        "{%0,%1,%2,%3}, {%4,%5,%6,%7}, {%8,%9}, {%0,%1,%2,%3};\n"
        : "+f"(c[0]), "+f"(c[1]), "+f"(c[2]), "+f"(c[3])
        : "r"(a[0]), "r"(a[1]), "r"(a[2]), "r"(a[3]), "r"(b[0]), "r"(b[1]));
}

// ---------------------------------------------------------------------------
// bf16 GEMM: C[m,n] = sc * sum_k A[m,k]*B[n,k] + bias[n]
// BM=128, BN=128, BK=64, 256 threads, 3-stage cp.async ring, ldmatrix frags.
// XOR-swizzled smem: off(row,chunk) = row*128 + ((chunk^(row&7))<<4)
// EPI==1: gelu + global min/max  |  EPI==2: plain
// ---------------------------------------------------------------------------
template <int EPI>
__global__ void __launch_bounds__(256, 2) k_gemm_bf(const float* __restrict__ bias,
                                                    float* __restrict__ Cout) {
    constexpr int Mn = MT;
    constexpr int Nn = (EPI == 1) ? HH : DD;
    constexpr int Kn = (EPI == 1) ? DD : HH;
    constexpr int BM = 128, BN = 128, BK = 64;
    constexpr int KT = Kn / BK;
    constexpr uint32_t STAGE = (BM + BN) * 128;   // 32 KB

    const __nv_bfloat16* __restrict__ A = (EPI == 1) ? g_xq : g_gq;
    const __nv_bfloat16* __restrict__ B = (EPI == 1) ? g_w1q : g_w2q;
    float* __restrict__ C = (EPI == 1) ? g_mid : Cout;

    extern __shared__ char smem[];
    const uint32_t sbase = (uint32_t)__cvta_generic_to_shared(smem);

    const int tid = threadIdx.x;
    const int warp = tid >> 5, lane = tid & 31;
    const int wm = warp & 1, wn = warp >> 1;      // 2x4 warps, warp tile 64x32
    const int g = lane >> 2, t = lane & 3;
    const int mBase = blockIdx.x * BM, nBase = blockIdx.y * BN;

    float acc[4][4][4];
#pragma unroll
    for (int i = 0; i < 4; i++)
#pragma unroll
        for (int j = 0; j < 4; j++)
#pragma unroll
            for (int k = 0; k < 4; k++) acc[i][j][k] = 0.f;

    // ---- stage loader: (BM+BN) rows x 8 chunks of 16B, 2048 total ----
    auto issue = [&](int s) {
        uint32_t sb = sbase + (uint32_t)(s % 3) * STAGE;
        const int kOff = s * BK;
#pragma unroll
        for (int ci = tid; ci < 2048; ci += 256) {
            int row = ci >> 3, c = ci & 7;
            uint32_t dst = sb + (uint32_t)(row * 128 + ((c ^ (row & 7)) << 4));
            if (row < BM) {
                int grow = mBase + row;
                bool ok = grow < Mn;
                int safe = ok ? grow : (Mn - 1);
                const __nv_bfloat16* gp = A + (size_t)safe * Kn + kOff + c * 8;
                int sz = ok ? 16 : 0;
                asm volatile("cp.async.cg.shared.global [%0], [%1], 16, %2;\n"
                             :: "r"(dst), "l"(gp), "r"(sz));
            } else {
                const __nv_bfloat16* gp = B + (size_t)(nBase + row - BM) * Kn + kOff + c * 8;
                asm volatile("cp.async.cg.shared.global [%0], [%1], 16, %2;\n"
                             :: "r"(dst), "l"(gp), "r"(16));
            }
        }
        asm volatile("cp.async.commit_group;\n");
    };

    auto compute = [&](int s) {
        uint32_t sa = sbase + (uint32_t)(s % 3) * STAGE;
        uint32_t sb = sa + (uint32_t)(BM * 128);
#pragma unroll
        for (int ks = 0; ks < 4; ks++) {
            uint32_t a[4][4], b[4][2];
#pragma unroll
            for (int i = 0; i < 4; i++) {
                int row = wm * 64 + i * 16 + (lane & 15);
                int chunk = 2 * ks + (lane >> 4);
                uint32_t addr = sa + (uint32_t)(row * 128 + ((chunk ^ (row & 7)) << 4));
                ldsm_x4(a[i][0], a[i][1], a[i][2], a[i][3], addr);
            }
#pragma unroll
            for (int jp = 0; jp < 2; jp++) {
                int q = lane >> 3;
                int nrow = wn * 32 + jp * 16 + (q >> 1) * 8 + (lane & 7);
                int chunk = 2 * ks + (q & 1);
                uint32_t addr = sb + (uint32_t)(nrow * 128 + ((chunk ^ (nrow & 7)) << 4));
                ldsm_x4(b[2 * jp][0], b[2 * jp][1], b[2 * jp + 1][0], b[2 * jp + 1][1], addr);
            }
#pragma unroll
            for (int i = 0; i < 4; i++)
#pragma unroll
                for (int j = 0; j < 4; j++) hmma(acc[i][j], a[i], b[j]);
        }
    };

    issue(0);
    issue(1);
    for (int kt = 0; kt < KT; kt++) {
        if (kt + 2 < KT) {
            issue(kt + 2);
            asm volatile("cp.async.wait_group 2;\n" ::: "memory");
        } else if (kt + 1 < KT) {
            asm volatile("cp.async.wait_group 1;\n" ::: "memory");
        } else {
            asm volatile("cp.async.wait_group 0;\n" ::: "memory");
        }
        __syncthreads();
        compute(kt);
        __syncthreads();
    }

    // ---- epilogue ----
    float sc;
    if (EPI == 1) {
        float s1 = fmaxf(g_stats[1] - g_stats[0], 1e-8f) / 255.0f;
        float s2 = fmaxf(g_stats[2], 1e-8f) / 127.0f;
        sc = s1 * s2;
    } else {
        float s1 = fmaxf(g_stats[5] - g_stats[4], 1e-8f) / 255.0f;
        float s2 = fmaxf(g_stats[3], 1e-8f) / 127.0f;
        sc = s1 * s2;
    }

    float lo = FBIG, hi = -FBIG;
#pragma unroll
    for (int j = 0; j < 4; j++) {
        int c = nBase + wn * 32 + j * 8 + 2 * t;
        float b0 = __ldg(bias + c), b1 = __ldg(bias + c + 1);
#pragma unroll
        for (int i = 0; i < 4; i++) {
            int row0 = mBase + wm * 64 + i * 16 + g;
            float v0 = sc * acc[i][j][0] + b0;
            float v1 = sc * acc[i][j][1] + b1;
            float v2 = sc * acc[i][j][2] + b0;
            float v3 = sc * acc[i][j][3] + b1;
            if (EPI == 1) { v0 = igelu(v0); v1 = igelu(v1); v2 = igelu(v2); v3 = igelu(v3); }
            if (row0 < Mn) {
                if (EPI == 1) { lo = fminf(lo, fminf(v0, v1)); hi = fmaxf(hi, fmaxf(v0, v1)); }
                *(float2*)(C + (size_t)row0 * Nn + c) = make_float2(v0, v1);
            }
            if (row0 + 8 < Mn) {
                if (EPI == 1) { lo = fminf(lo, fminf(v2, v3)); hi = fmaxf(hi, fmaxf(v2, v3)); }
                *(float2*)(C + (size_t)(row0 + 8) * Nn + c) = make_float2(v2, v3);
            }
        }
    }

    if (EPI == 1) {
        for (int o = 16; o; o >>= 1) {
            lo = fminf(lo, __shfl_xor_sync(0xffffffffu, lo, o));
            hi = fmaxf(hi, __shfl_xor_sync(0xffffffffu, hi, o));
        }
        __shared__ float rlo[8], rhi[8];
        if (lane == 0) { rlo[warp] = lo; rhi[warp] = hi; }
        __syncthreads();
        if (tid == 0) {
            for (int i = 1; i < 8; i++) { lo = fminf(lo, rlo[i]); hi = fmaxf(hi, rhi[i]); }
            atomicMinF(&g_stats[4], lo);
            atomicMaxF(&g_stats[5], hi);
        }
    }
}

extern "C" void kernel_launch(void* const* d_in, const int* in_sizes, int n_in,
                              void* d_out, int out_size) {
    const float* x  = (const float*)d_in[0];
    const float* w1 = (const float*)d_in[1];
    const float* b1 = (const float*)d_in[2];
    const float* w2 = (const float*)d_in[3];
    const float* b2 = (const float*)d_in[4];
    float* out = (float*)d_out;

    constexpr int SMEM_BYTES = 3 * (128 + 128) * 128;   // 98304 = 96 KB
    cudaFuncSetAttribute(k_gemm_bf<1>, cudaFuncAttributeMaxDynamicSharedMemorySize, SMEM_BYTES);
    cudaFuncSetAttribute(k_gemm_bf<2>, cudaFuncAttributeMaxDynamicSharedMemorySize, SMEM_BYTES);

    k_init<<<1, 1>>>();
    k_minmax<<<1024, 256>>>(x, MT * DD / 4, 0);
    k_absmax<<<512, 256>>>(w1, HH * DD / 4, 2);
    k_absmax<<<512, 256>>>(w2, DD * HH / 4, 3);
    k_quant_x<<<2048, 256>>>(x, MT * DD / 4);
    k_quant_w<<<512, 256>>>(w1, HH * DD / 4, 2, 0);
    k_quant_w<<<512, 256>>>(w2, DD * HH / 4, 3, 1);

    dim3 grid1((MT + 127) / 128, HH / 128);
    k_gemm_bf<1><<<grid1, 256, SMEM_BYTES>>>(b1, nullptr);

    k_quant_g<<<4096, 256>>>((int)((size_t)MT * HH / 4));

    dim3 grid2((MT + 127) / 128, DD / 128);
    k_gemm_bf<2><<<grid2, 256, SMEM_BYTES>>>(b2, out);
}

// round 6
// speedup vs baseline: 2.5577x; 1.0235x over previous
#include <cuda_runtime.h>
#include <cuda_bf16.h>
#include <cstdint>

#define DEVI static __device__ __forceinline__

static constexpr int MT = 64 * 197;   // 12608 rows
static constexpr int DD = 768;
static constexpr int HH = 3072;
static constexpr float FBIG = 3.0e38f;

// Scratch (allocation-free rule: __device__ globals)
__device__ __nv_bfloat16 g_xq[MT * DD];          // (q - zp) codes of x, exact ints in bf16
__device__ __nv_bfloat16 g_w1q[HH * DD];         // w1 codes
__device__ __nv_bfloat16 g_w2q[DD * HH];         // w2 codes
__device__ float         g_mid[(size_t)MT * HH]; // gelu output fp32
__device__ __nv_bfloat16 g_gq[(size_t)MT * HH];  // (q - zp) codes of g
__device__ float         g_stats[6];             // xmin,xmax,w1max,w2max,gmin,gmax

DEVI void atomicMinF(float* a, float v) {
    int* ai = (int*)a;
    int old = *ai;
    while (__int_as_float(old) > v) {
        int as = old;
        old = atomicCAS(ai, as, __float_as_int(v));
        if (old == as) break;
    }
}
DEVI void atomicMaxF(float* a, float v) {
    int* ai = (int*)a;
    int old = *ai;
    while (__int_as_float(old) < v) {
        int as = old;
        old = atomicCAS(ai, as, __float_as_int(v));
        if (old == as) break;
    }
}

__global__ void k_init() {
    g_stats[0] = FBIG;  g_stats[1] = -FBIG;
    g_stats[2] = 0.f;   g_stats[3] = 0.f;
    g_stats[4] = FBIG;  g_stats[5] = -FBIG;
}

// ---- fused stats: blocks [0,1024) minmax(x), [1024,1280) absmax(w1), [1280,1536) absmax(w2)
__global__ void k_stats(const float* __restrict__ x, const float* __restrict__ w1,
                        const float* __restrict__ w2) {
    int b = blockIdx.x;
    const float* src;
    int n4, nblk, b0, mode, sidx;
    if (b < 1024)      { src = x;  n4 = MT * DD / 4; nblk = 1024; b0 = 0;    mode = 0; sidx = 0; }
    else if (b < 1280) { src = w1; n4 = HH * DD / 4; nblk = 256;  b0 = 1024; mode = 1; sidx = 2; }
    else               { src = w2; n4 = DD * HH / 4; nblk = 256;  b0 = 1280; mode = 1; sidx = 3; }

    float lo = FBIG, hi = -FBIG;
    int st = nblk * blockDim.x;
    for (int i = (b - b0) * blockDim.x + threadIdx.x; i < n4; i += st) {
        float4 v = ((const float4*)src)[i];
        if (mode == 0) {
            lo = fminf(lo, fminf(fminf(v.x, v.y), fminf(v.z, v.w)));
            hi = fmaxf(hi, fmaxf(fmaxf(v.x, v.y), fmaxf(v.z, v.w)));
        } else {
            hi = fmaxf(hi, fmaxf(fmaxf(fabsf(v.x), fabsf(v.y)), fmaxf(fabsf(v.z), fabsf(v.w))));
        }
    }
    for (int o = 16; o; o >>= 1) {
        lo = fminf(lo, __shfl_xor_sync(0xffffffffu, lo, o));
        hi = fmaxf(hi, __shfl_xor_sync(0xffffffffu, hi, o));
    }
    __shared__ float slo[8], shi[8];
    int w = threadIdx.x >> 5;
    if ((threadIdx.x & 31) == 0) { slo[w] = lo; shi[w] = hi; }
    __syncthreads();
    if (threadIdx.x == 0) {
        for (int i = 1; i < 8; i++) { lo = fminf(lo, slo[i]); hi = fmaxf(hi, shi[i]); }
        if (mode == 0) { atomicMinF(&g_stats[0], lo); atomicMaxF(&g_stats[1], hi); }
        else           { atomicMaxF(&g_stats[sidx], hi); }
    }
}

DEVI float quant_act_one(float v, float s, float zp) {
    return fminf(fmaxf(rintf(v / s) + zp, 0.f), 255.f) - zp;
}

// ---- fused quant: blocks [0,2048) x, [2048,2560) w1, [2560,3072) w2
__global__ void k_quant(const float* __restrict__ x, const float* __restrict__ w1,
                        const float* __restrict__ w2) {
    int b = blockIdx.x;
    if (b < 2048) {
        float lo = g_stats[0], hi = g_stats[1];
        float s = fmaxf(hi - lo, 1e-8f) / 255.0f;
        float zp = rintf(-lo / s);
        __nv_bfloat162* qp = (__nv_bfloat162*)g_xq;
        int n4 = MT * DD / 4, st = 2048 * blockDim.x;
        for (int i = b * blockDim.x + threadIdx.x; i < n4; i += st) {
            float4 v = ((const float4*)x)[i];
            qp[2 * i]     = __floats2bfloat162_rn(quant_act_one(v.x, s, zp), quant_act_one(v.y, s, zp));
            qp[2 * i + 1] = __floats2bfloat162_rn(quant_act_one(v.z, s, zp), quant_act_one(v.w, s, zp));
        }
    } else {
        int which = (b >= 2560);
        const float* w = which ? w2 : w1;
        float s = fmaxf(g_stats[which ? 3 : 2], 1e-8f) / 127.0f;
        __nv_bfloat162* qp = (__nv_bfloat162*)(which ? g_w2q : g_w1q);
        int bb = b - (which ? 2560 : 2048);
        int n4 = HH * DD / 4, st = 512 * blockDim.x;
        for (int i = bb * blockDim.x + threadIdx.x; i < n4; i += st) {
            float4 v = ((const float4*)w)[i];
            float q0 = fminf(fmaxf(rintf(v.x / s), -128.f), 127.f);
            float q1 = fminf(fmaxf(rintf(v.y / s), -128.f), 127.f);
            float q2 = fminf(fmaxf(rintf(v.z / s), -128.f), 127.f);
            float q3 = fminf(fmaxf(rintf(v.w / s), -128.f), 127.f);
            qp[2 * i]     = __floats2bfloat162_rn(q0, q1);
            qp[2 * i + 1] = __floats2bfloat162_rn(q2, q3);
        }
    }
}

__global__ void k_quant_g(int n4) {
    float lo = g_stats[4], hi = g_stats[5];
    float s = fmaxf(hi - lo, 1e-8f) / 255.0f;
    float zp = rintf(-lo / s);
    __nv_bfloat162* qp = (__nv_bfloat162*)g_gq;
    const float4* x = (const float4*)g_mid;
    int st = gridDim.x * blockDim.x;
    for (int i = blockIdx.x * blockDim.x + threadIdx.x; i < n4; i += st) {
        float4 v = __ldcs(x + i);   // streaming read: mid is read-once
        qp[2 * i]     = __floats2bfloat162_rn(quant_act_one(v.x, s, zp), quant_act_one(v.y, s, zp));
        qp[2 * i + 1] = __floats2bfloat162_rn(quant_act_one(v.z, s, zp), quant_act_one(v.w, s, zp));
    }
}

DEVI float igelu(float x) {
    float tt = x * 0.70710678118654752440f;
    float at = fminf(fabsf(tt), 1.769f);
    float dd = at - 1.769f;
    float L = fmaf(-0.2888f, dd * dd, 1.0f);
    L = copysignf(L, tt);
    return x * 0.5f * (1.0f + L);
}

DEVI void ldsm_x4(uint32_t& r0, uint32_t& r1, uint32_t& r2, uint32_t& r3, uint32_t addr) {
    asm volatile("ldmatrix.sync.aligned.m8n8.x4.shared.b16 {%0,%1,%2,%3}, [%4];"
                 : "=r"(r0), "=r"(r1), "=r"(r2), "=r"(r3) : "r"(addr));
}
DEVI void hmma(float* c, const uint32_t* a, const uint32_t* b) {
    asm volatile(
        "mma.sync.aligned.m16n8k16.row.col.f32.bf16.bf16.f32 "
        "{%0,%1,%2,%3}, {%4,%5,%6,%7}, {%8,%9}, {%0,%1,%2,%3};\n"
        : "+f"(c[0]), "+f"(c[1]), "+f"(c[2]), "+f"(c[3])
        : "r"(a[0]), "r"(a[1]), "r"(a[2]), "r"(a[3]), "r"(b[0]), "r"(b[1]));
}

// ---------------------------------------------------------------------------
// bf16 GEMM: C[m,n] = sc * sum_k A[m,k]*B[n,k] + bias[n]
// BM=128, BN=128, BK=64, 256 threads, 3-stage cp.async ring, ldmatrix frags.
// ---------------------------------------------------------------------------
template <int EPI>
__global__ void __launch_bounds__(256, 2) k_gemm_bf(const float* __restrict__ bias,
                                                    float* __restrict__ Cout) {
    constexpr int Mn = MT;
    constexpr int Nn = (EPI == 1) ? HH : DD;
    constexpr int Kn = (EPI == 1) ? DD : HH;
    constexpr int BM = 128, BN = 128, BK = 64;
    constexpr int KT = Kn / BK;
    constexpr uint32_t STAGE = (BM + BN) * 128;   // 32 KB

    const __nv_bfloat16* __restrict__ A = (EPI == 1) ? g_xq : g_gq;
    const __nv_bfloat16* __restrict__ B = (EPI == 1) ? g_w1q : g_w2q;
    float* __restrict__ C = (EPI == 1) ? g_mid : Cout;

    extern __shared__ char smem[];
    const uint32_t sbase = (uint32_t)__cvta_generic_to_shared(smem);

    const int tid = threadIdx.x;
    const int warp = tid >> 5, lane = tid & 31;
    const int wm = warp & 1, wn = warp >> 1;      // 2x4 warps, warp tile 64x32
    const int g = lane >> 2, t = lane & 3;
    const int mBase = blockIdx.x * BM, nBase = blockIdx.y * BN;

    float acc[4][4][4];
#pragma unroll
    for (int i = 0; i < 4; i++)
#pragma unroll
        for (int j = 0; j < 4; j++)
#pragma unroll
            for (int k = 0; k < 4; k++) acc[i][j][k] = 0.f;

    auto issue = [&](int s) {
        uint32_t sb = sbase + (uint32_t)(s % 3) * STAGE;
        const int kOff = s * BK;
#pragma unroll
        for (int ci = tid; ci < 2048; ci += 256) {
            int row = ci >> 3, c = ci & 7;
            uint32_t dst = sb + (uint32_t)(row * 128 + ((c ^ (row & 7)) << 4));
            if (row < BM) {
                int grow = mBase + row;
                bool ok = grow < Mn;
                int safe = ok ? grow : (Mn - 1);
                const __nv_bfloat16* gp = A + (size_t)safe * Kn + kOff + c * 8;
                int sz = ok ? 16 : 0;
                asm volatile("cp.async.cg.shared.global [%0], [%1], 16, %2;\n"
                             :: "r"(dst), "l"(gp), "r"(sz));
            } else {
                const __nv_bfloat16* gp = B + (size_t)(nBase + row - BM) * Kn + kOff + c * 8;
                asm volatile("cp.async.cg.shared.global [%0], [%1], 16, %2;\n"
                             :: "r"(dst), "l"(gp), "r"(16));
            }
        }
        asm volatile("cp.async.commit_group;\n");
    };

    auto compute = [&](int s) {
        uint32_t sa = sbase + (uint32_t)(s % 3) * STAGE;
        uint32_t sb = sa + (uint32_t)(BM * 128);
#pragma unroll
        for (int ks = 0; ks < 4; ks++) {
            uint32_t a[4][4], b[4][2];
#pragma unroll
            for (int i = 0; i < 4; i++) {
                int row = wm * 64 + i * 16 + (lane & 15);
                int chunk = 2 * ks + (lane >> 4);
                uint32_t addr = sa + (uint32_t)(row * 128 + ((chunk ^ (row & 7)) << 4));
                ldsm_x4(a[i][0], a[i][1], a[i][2], a[i][3], addr);
            }
#pragma unroll
            for (int jp = 0; jp < 2; jp++) {
                int q = lane >> 3;
                int nrow = wn * 32 + jp * 16 + (q >> 1) * 8 + (lane & 7);
                int chunk = 2 * ks + (q & 1);
                uint32_t addr = sb + (uint32_t)(nrow * 128 + ((chunk ^ (nrow & 7)) << 4));
                ldsm_x4(b[2 * jp][0], b[2 * jp][1], b[2 * jp + 1][0], b[2 * jp + 1][1], addr);
            }
#pragma unroll
            for (int i = 0; i < 4; i++)
#pragma unroll
                for (int j = 0; j < 4; j++) hmma(acc[i][j], a[i], b[j]);
        }
    };

    issue(0);
    issue(1);
    for (int kt = 0; kt < KT; kt++) {
        if (kt + 2 < KT) {
            issue(kt + 2);
            asm volatile("cp.async.wait_group 2;\n" ::: "memory");
        } else if (kt + 1 < KT) {
            asm volatile("cp.async.wait_group 1;\n" ::: "memory");
        } else {
            asm volatile("cp.async.wait_group 0;\n" ::: "memory");
        }
        __syncthreads();
        compute(kt);
        __syncthreads();
    }

    // ---- epilogue ----
    float sc;
    if (EPI == 1) {
        float s1 = fmaxf(g_stats[1] - g_stats[0], 1e-8f) / 255.0f;
        float s2 = fmaxf(g_stats[2], 1e-8f) / 127.0f;
        sc = s1 * s2;
    } else {
        float s1 = fmaxf(g_stats[5] - g_stats[4], 1e-8f) / 255.0f;
        float s2 = fmaxf(g_stats[3], 1e-8f) / 127.0f;
        sc = s1 * s2;
    }

    float lo = FBIG, hi = -FBIG;
#pragma unroll
    for (int j = 0; j < 4; j++) {
        int c = nBase + wn * 32 + j * 8 + 2 * t;
        float b0 = __ldg(bias + c), b1 = __ldg(bias + c + 1);
#pragma unroll
        for (int i = 0; i < 4; i++) {
            int row0 = mBase + wm * 64 + i * 16 + g;
            float v0 = sc * acc[i][j][0] + b0;
            float v1 = sc * acc[i][j][1] + b1;
            float v2 = sc * acc[i][j][2] + b0;
            float v3 = sc * acc[i][j][3] + b1;
            if (EPI == 1) { v0 = igelu(v0); v1 = igelu(v1); v2 = igelu(v2); v3 = igelu(v3); }
            if (row0 < Mn) {
                if (EPI == 1) {
                    lo = fminf(lo, fminf(v0, v1)); hi = fmaxf(hi, fmaxf(v0, v1));
                    __stcs((float2*)(C + (size_t)row0 * Nn + c), make_float2(v0, v1));
                } else {
                    *(float2*)(C + (size_t)row0 * Nn + c) = make_float2(v0, v1);
                }
            }
            if (row0 + 8 < Mn) {
                if (EPI == 1) {
                    lo = fminf(lo, fminf(v2, v3)); hi = fmaxf(hi, fmaxf(v2, v3));
                    __stcs((float2*)(C + (size_t)(row0 + 8) * Nn + c), make_float2(v2, v3));
                } else {
                    *(float2*)(C + (size_t)(row0 + 8) * Nn + c) = make_float2(v2, v3);
                }
            }
        }
    }

    if (EPI == 1) {
        for (int o = 16; o; o >>= 1) {
            lo = fminf(lo, __shfl_xor_sync(0xffffffffu, lo, o));
            hi = fmaxf(hi, __shfl_xor_sync(0xffffffffu, hi, o));
        }
        __shared__ float rlo[8], rhi[8];
        if (lane == 0) { rlo[warp] = lo; rhi[warp] = hi; }
        __syncthreads();
        if (tid == 0) {
            for (int i = 1; i < 8; i++) { lo = fminf(lo, rlo[i]); hi = fmaxf(hi, rhi[i]); }
            atomicMinF(&g_stats[4], lo);
            atomicMaxF(&g_stats[5], hi);
        }
    }
}

extern "C" void kernel_launch(void* const* d_in, const int* in_sizes, int n_in,
                              void* d_out, int out_size) {
    const float* x  = (const float*)d_in[0];
    const float* w1 = (const float*)d_in[1];
    const float* b1 = (const float*)d_in[2];
    const float* w2 = (const float*)d_in[3];
    const float* b2 = (const float*)d_in[4];
    float* out = (float*)d_out;

    constexpr int SMEM_BYTES = 3 * (128 + 128) * 128;   // 96 KB
    cudaFuncSetAttribute(k_gemm_bf<1>, cudaFuncAttributeMaxDynamicSharedMemorySize, SMEM_BYTES);
    cudaFuncSetAttribute(k_gemm_bf<2>, cudaFuncAttributeMaxDynamicSharedMemorySize, SMEM_BYTES);

    k_init<<<1, 1>>>();
    k_stats<<<1536, 256>>>(x, w1, w2);
    k_quant<<<3072, 256>>>(x, w1, w2);

    dim3 grid1((MT + 127) / 128, HH / 128);
    k_gemm_bf<1><<<grid1, 256, SMEM_BYTES>>>(b1, nullptr);

    k_quant_g<<<4096, 256>>>((int)((size_t)MT * HH / 4));

    dim3 grid2((MT + 127) / 128, DD / 128);
    k_gemm_bf<2><<<grid2, 256, SMEM_BYTES>>>(b2, out);
}

// round 7
// speedup vs baseline: 2.5666x; 1.0035x over previous
#include <cuda_runtime.h>
#include <cuda_bf16.h>
#include <cstdint>

#define DEVI static __device__ __forceinline__

static constexpr int MT = 64 * 197;   // 12608 rows
static constexpr int DD = 768;
static constexpr int HH = 3072;
static constexpr float FBIG = 3.0e38f;

// Scratch (allocation-free rule: __device__ globals)
__device__ __nv_bfloat16 g_xq[MT * DD];          // (q - zp) codes of x, exact ints in bf16
__device__ __nv_bfloat16 g_w1q[HH * DD];         // w1 codes
__device__ __nv_bfloat16 g_w2q[DD * HH];         // w2 codes
__device__ float         g_mid[(size_t)MT * HH]; // gelu output fp32
__device__ __nv_bfloat16 g_gq[(size_t)MT * HH];  // (q - zp) codes of g
__device__ float         g_stats[6];             // xmin,xmax,w1max,w2max,gmin,gmax

DEVI void atomicMinF(float* a, float v) {
    int* ai = (int*)a;
    int old = *ai;
    while (__int_as_float(old) > v) {
        int as = old;
        old = atomicCAS(ai, as, __float_as_int(v));
        if (old == as) break;
    }
}
DEVI void atomicMaxF(float* a, float v) {
    int* ai = (int*)a;
    int old = *ai;
    while (__int_as_float(old) < v) {
        int as = old;
        old = atomicCAS(ai, as, __float_as_int(v));
        if (old == as) break;
    }
}

__global__ void k_init() {
    g_stats[0] = FBIG;  g_stats[1] = -FBIG;
    g_stats[2] = 0.f;   g_stats[3] = 0.f;
    g_stats[4] = FBIG;  g_stats[5] = -FBIG;
}

// ---- fused stats: blocks [0,1024) minmax(x), [1024,1280) absmax(w1), [1280,1536) absmax(w2)
__global__ void k_stats(const float* __restrict__ x, const float* __restrict__ w1,
                        const float* __restrict__ w2) {
    int b = blockIdx.x;
    const float* src;
    int n4, nblk, b0, mode, sidx;
    if (b < 1024)      { src = x;  n4 = MT * DD / 4; nblk = 1024; b0 = 0;    mode = 0; sidx = 0; }
    else if (b < 1280) { src = w1; n4 = HH * DD / 4; nblk = 256;  b0 = 1024; mode = 1; sidx = 2; }
    else               { src = w2; n4 = DD * HH / 4; nblk = 256;  b0 = 1280; mode = 1; sidx = 3; }

    float lo = FBIG, hi = -FBIG;
    int st = nblk * blockDim.x;
    for (int i = (b - b0) * blockDim.x + threadIdx.x; i < n4; i += st) {
        float4 v = ((const float4*)src)[i];
        if (mode == 0) {
            lo = fminf(lo, fminf(fminf(v.x, v.y), fminf(v.z, v.w)));
            hi = fmaxf(hi, fmaxf(fmaxf(v.x, v.y), fmaxf(v.z, v.w)));
        } else {
            hi = fmaxf(hi, fmaxf(fmaxf(fabsf(v.x), fabsf(v.y)), fmaxf(fabsf(v.z), fabsf(v.w))));
        }
    }
    for (int o = 16; o; o >>= 1) {
        lo = fminf(lo, __shfl_xor_sync(0xffffffffu, lo, o));
        hi = fmaxf(hi, __shfl_xor_sync(0xffffffffu, hi, o));
    }
    __shared__ float slo[8], shi[8];
    int w = threadIdx.x >> 5;
    if ((threadIdx.x & 31) == 0) { slo[w] = lo; shi[w] = hi; }
    __syncthreads();
    if (threadIdx.x == 0) {
        for (int i = 1; i < 8; i++) { lo = fminf(lo, slo[i]); hi = fmaxf(hi, shi[i]); }
        if (mode == 0) { atomicMinF(&g_stats[0], lo); atomicMaxF(&g_stats[1], hi); }
        else           { atomicMaxF(&g_stats[sidx], hi); }
    }
}

DEVI float quant_act_one(float v, float s, float zp) {
    return fminf(fmaxf(rintf(v / s) + zp, 0.f), 255.f) - zp;
}

// ---- fused quant: blocks [0,2048) x, [2048,2560) w1, [2560,3072) w2
__global__ void k_quant(const float* __restrict__ x, const float* __restrict__ w1,
                        const float* __restrict__ w2) {
    int b = blockIdx.x;
    if (b < 2048) {
        float lo = g_stats[0], hi = g_stats[1];
        float s = fmaxf(hi - lo, 1e-8f) / 255.0f;
        float zp = rintf(-lo / s);
        __nv_bfloat162* qp = (__nv_bfloat162*)g_xq;
        int n4 = MT * DD / 4, st = 2048 * blockDim.x;
        for (int i = b * blockDim.x + threadIdx.x; i < n4; i += st) {
            float4 v = ((const float4*)x)[i];
            qp[2 * i]     = __floats2bfloat162_rn(quant_act_one(v.x, s, zp), quant_act_one(v.y, s, zp));
            qp[2 * i + 1] = __floats2bfloat162_rn(quant_act_one(v.z, s, zp), quant_act_one(v.w, s, zp));
        }
    } else {
        int which = (b >= 2560);
        const float* w = which ? w2 : w1;
        float s = fmaxf(g_stats[which ? 3 : 2], 1e-8f) / 127.0f;
        __nv_bfloat162* qp = (__nv_bfloat162*)(which ? g_w2q : g_w1q);
        int bb = b - (which ? 2560 : 2048);
        int n4 = HH * DD / 4, st = 512 * blockDim.x;
        for (int i = bb * blockDim.x + threadIdx.x; i < n4; i += st) {
            float4 v = ((const float4*)w)[i];
            float q0 = fminf(fmaxf(rintf(v.x / s), -128.f), 127.f);
            float q1 = fminf(fmaxf(rintf(v.y / s), -128.f), 127.f);
            float q2 = fminf(fmaxf(rintf(v.z / s), -128.f), 127.f);
            float q3 = fminf(fmaxf(rintf(v.w / s), -128.f), 127.f);
            qp[2 * i]     = __floats2bfloat162_rn(q0, q1);
            qp[2 * i + 1] = __floats2bfloat162_rn(q2, q3);
        }
    }
}

__global__ void k_quant_g(int n4) {
    float lo = g_stats[4], hi = g_stats[5];
    float s = fmaxf(hi - lo, 1e-8f) / 255.0f;
    float zp = rintf(-lo / s);
    __nv_bfloat162* qp = (__nv_bfloat162*)g_gq;
    const float4* x = (const float4*)g_mid;
    int st = gridDim.x * blockDim.x;
    for (int i = blockIdx.x * blockDim.x + threadIdx.x; i < n4; i += st) {
        float4 v = __ldcs(x + i);   // streaming read: mid is read-once
        qp[2 * i]     = __floats2bfloat162_rn(quant_act_one(v.x, s, zp), quant_act_one(v.y, s, zp));
        qp[2 * i + 1] = __floats2bfloat162_rn(quant_act_one(v.z, s, zp), quant_act_one(v.w, s, zp));
    }
}

DEVI float igelu(float x) {
    float tt = x * 0.70710678118654752440f;
    float at = fminf(fabsf(tt), 1.769f);
    float dd = at - 1.769f;
    float L = fmaf(-0.2888f, dd * dd, 1.0f);
    L = copysignf(L, tt);
    return x * 0.5f * (1.0f + L);
}

DEVI void ldsm_x4(uint32_t& r0, uint32_t& r1, uint32_t& r2, uint32_t& r3, uint32_t addr) {
    asm volatile("ldmatrix.sync.aligned.m8n8.x4.shared.b16 {%0,%1,%2,%3}, [%4];"
                 : "=r"(r0), "=r"(r1), "=r"(r2), "=r"(r3) : "r"(addr));
}
DEVI void hmma(float* c, const uint32_t* a, const uint32_t* b) {
    asm volatile(
        "mma.sync.aligned.m16n8k16.row.col.f32.bf16.bf16.f32 "
        "{%0,%1,%2,%3}, {%4,%5,%6,%7}, {%8,%9}, {%0,%1,%2,%3};\n"
        : "+f"(c[0]), "+f"(c[1]), "+f"(c[2]), "+f"(c[3])
        : "r"(a[0]), "r"(a[1]), "r"(a[2]), "r"(a[3]), "r"(b[0]), "r"(b[1]));
}

// ---------------------------------------------------------------------------
// bf16 GEMM: C[m,n] = sc * sum_k A[m,k]*B[n,k] + bias[n]
// BM=128, BN=128, BK=64, 256 threads, 3-stage cp.async ring, ldmatrix frags.
// Single __syncthreads per mainloop iteration:
//   [wait_group; sync; issue(kt+2); compute(kt)]
// issue(kt+2) writes buffer (kt-1)%3, which all warps finished reading in
// compute(kt-1) BEFORE the sync at the top of iteration kt -> race-free.
// ---------------------------------------------------------------------------
template <int EPI>
__global__ void __launch_bounds__(256, 2) k_gemm_bf(const float* __restrict__ bias,
                                                    float* __restrict__ Cout) {
    constexpr int Mn = MT;
    constexpr int Nn = (EPI == 1) ? HH : DD;
    constexpr int Kn = (EPI == 1) ? DD : HH;
    constexpr int BM = 128, BN = 128, BK = 64;
    constexpr int KT = Kn / BK;
    constexpr uint32_t STAGE = (BM + BN) * 128;   // 32 KB

    const __nv_bfloat16* __restrict__ A = (EPI == 1) ? g_xq : g_gq;
    const __nv_bfloat16* __restrict__ B = (EPI == 1) ? g_w1q : g_w2q;
    float* __restrict__ C = (EPI == 1) ? g_mid : Cout;

    extern __shared__ char smem[];
    const uint32_t sbase = (uint32_t)__cvta_generic_to_shared(smem);

    const int tid = threadIdx.x;
    const int warp = tid >> 5, lane = tid & 31;
    const int wm = warp & 1, wn = warp >> 1;      // 2x4 warps, warp tile 64x32
    const int g = lane >> 2, t = lane & 3;
    const int mBase = blockIdx.x * BM, nBase = blockIdx.y * BN;

    float acc[4][4][4];
#pragma unroll
    for (int i = 0; i < 4; i++)
#pragma unroll
        for (int j = 0; j < 4; j++)
#pragma unroll
            for (int k = 0; k < 4; k++) acc[i][j][k] = 0.f;

    auto issue = [&](int s) {
        uint32_t sb = sbase + (uint32_t)(s % 3) * STAGE;
        const int kOff = s * BK;
#pragma unroll
        for (int ci = tid; ci < 2048; ci += 256) {
            int row = ci >> 3, c = ci & 7;
            uint32_t dst = sb + (uint32_t)(row * 128 + ((c ^ (row & 7)) << 4));
            if (row < BM) {
                int grow = mBase + row;
                bool ok = grow < Mn;
                int safe = ok ? grow : (Mn - 1);
                const __nv_bfloat16* gp = A + (size_t)safe * Kn + kOff + c * 8;
                int sz = ok ? 16 : 0;
                asm volatile("cp.async.cg.shared.global [%0], [%1], 16, %2;\n"
                             :: "r"(dst), "l"(gp), "r"(sz));
            } else {
                const __nv_bfloat16* gp = B + (size_t)(nBase + row - BM) * Kn + kOff + c * 8;
                asm volatile("cp.async.cg.shared.global [%0], [%1], 16, %2;\n"
                             :: "r"(dst), "l"(gp), "r"(16));
            }
        }
        asm volatile("cp.async.commit_group;\n");
    };

    auto compute = [&](int s) {
        uint32_t sa = sbase + (uint32_t)(s % 3) * STAGE;
        uint32_t sb = sa + (uint32_t)(BM * 128);
#pragma unroll
        for (int ks = 0; ks < 4; ks++) {
            uint32_t a[4][4], b[4][2];
#pragma unroll
            for (int i = 0; i < 4; i++) {
                int row = wm * 64 + i * 16 + (lane & 15);
                int chunk = 2 * ks + (lane >> 4);
                uint32_t addr = sa + (uint32_t)(row * 128 + ((chunk ^ (row & 7)) << 4));
                ldsm_x4(a[i][0], a[i][1], a[i][2], a[i][3], addr);
            }
#pragma unroll
            for (int jp = 0; jp < 2; jp++) {
                int q = lane >> 3;
                int nrow = wn * 32 + jp * 16 + (q >> 1) * 8 + (lane & 7);
                int chunk = 2 * ks + (q & 1);
                uint32_t addr = sb + (uint32_t)(nrow * 128 + ((chunk ^ (nrow & 7)) << 4));
                ldsm_x4(b[2 * jp][0], b[2 * jp][1], b[2 * jp + 1][0], b[2 * jp + 1][1], addr);
            }
#pragma unroll
            for (int i = 0; i < 4; i++)
#pragma unroll
                for (int j = 0; j < 4; j++) hmma(acc[i][j], a[i], b[j]);
        }
    };

    issue(0);
    issue(1);
    for (int kt = 0; kt < KT; kt++) {
        if (kt + 1 < KT) asm volatile("cp.async.wait_group 1;\n" ::: "memory");
        else             asm volatile("cp.async.wait_group 0;\n" ::: "memory");
        __syncthreads();
        if (kt + 2 < KT) issue(kt + 2);
        compute(kt);
    }

    // ---- epilogue ----
    float sc;
    if (EPI == 1) {
        float s1 = fmaxf(g_stats[1] - g_stats[0], 1e-8f) / 255.0f;
        float s2 = fmaxf(g_stats[2], 1e-8f) / 127.0f;
        sc = s1 * s2;
    } else {
        float s1 = fmaxf(g_stats[5] - g_stats[4], 1e-8f) / 255.0f;
        float s2 = fmaxf(g_stats[3], 1e-8f) / 127.0f;
        sc = s1 * s2;
    }

    float lo = FBIG, hi = -FBIG;
#pragma unroll
    for (int j = 0; j < 4; j++) {
        int c = nBase + wn * 32 + j * 8 + 2 * t;
        float b0 = __ldg(bias + c), b1 = __ldg(bias + c + 1);
#pragma unroll
        for (int i = 0; i < 4; i++) {
            int row0 = mBase + wm * 64 + i * 16 + g;
            float v0 = sc * acc[i][j][0] + b0;
            float v1 = sc * acc[i][j][1] + b1;
            float v2 = sc * acc[i][j][2] + b0;
            float v3 = sc * acc[i][j][3] + b1;
            if (EPI == 1) { v0 = igelu(v0); v1 = igelu(v1); v2 = igelu(v2); v3 = igelu(v3); }
            if (row0 < Mn) {
                if (EPI == 1) {
                    lo = fminf(lo, fminf(v0, v1)); hi = fmaxf(hi, fmaxf(v0, v1));
                    __stcs((float2*)(C + (size_t)row0 * Nn + c), make_float2(v0, v1));
                } else {
                    *(float2*)(C + (size_t)row0 * Nn + c) = make_float2(v0, v1);
                }
            }
            if (row0 + 8 < Mn) {
                if (EPI == 1) {
                    lo = fminf(lo, fminf(v2, v3)); hi = fmaxf(hi, fmaxf(v2, v3));
                    __stcs((float2*)(C + (size_t)(row0 + 8) * Nn + c), make_float2(v2, v3));
                } else {
                    *(float2*)(C + (size_t)(row0 + 8) * Nn + c) = make_float2(v2, v3);
                }
            }
        }
    }

    if (EPI == 1) {
        for (int o = 16; o; o >>= 1) {
            lo = fminf(lo, __shfl_xor_sync(0xffffffffu, lo, o));
            hi = fmaxf(hi, __shfl_xor_sync(0xffffffffu, hi, o));
        }
        __shared__ float rlo[8], rhi[8];
        if (lane == 0) { rlo[warp] = lo; rhi[warp] = hi; }
        __syncthreads();
        if (tid == 0) {
            for (int i = 1; i < 8; i++) { lo = fminf(lo, rlo[i]); hi = fmaxf(hi, rhi[i]); }
            atomicMinF(&g_stats[4], lo);
            atomicMaxF(&g_stats[5], hi);
        }
    }
}

extern "C" void kernel_launch(void* const* d_in, const int* in_sizes, int n_in,
                              void* d_out, int out_size) {
    const float* x  = (const float*)d_in[0];
    const float* w1 = (const float*)d_in[1];
    const float* b1 = (const float*)d_in[2];
    const float* w2 = (const float*)d_in[3];
    const float* b2 = (const float*)d_in[4];
    float* out = (float*)d_out;

    constexpr int SMEM_BYTES = 3 * (128 + 128) * 128;   // 96 KB
    cudaFuncSetAttribute(k_gemm_bf<1>, cudaFuncAttributeMaxDynamicSharedMemorySize, SMEM_BYTES);
    cudaFuncSetAttribute(k_gemm_bf<2>, cudaFuncAttributeMaxDynamicSharedMemorySize, SMEM_BYTES);

    k_init<<<1, 1>>>();
    k_stats<<<1536, 256>>>(x, w1, w2);
    k_quant<<<3072, 256>>>(x, w1, w2);

    dim3 grid1((MT + 127) / 128, HH / 128);
    k_gemm_bf<1><<<grid1, 256, SMEM_BYTES>>>(b1, nullptr);

    k_quant_g<<<4096, 256>>>((int)((size_t)MT * HH / 4));

    dim3 grid2((MT + 127) / 128, DD / 128);
    k_gemm_bf<2><<<grid2, 256, SMEM_BYTES>>>(b2, out);
}